// round 12
// baseline (speedup 1.0000x reference)
#include <cuda_runtime.h>
#include <cuda_bf16.h>
#include <cstdint>

// Problem constants
#define BB 16
#define KK 256
#define ZZ 128
#define HH 128
#define NROWS (BB * KK)   // 4096

// fp32 scratch (K2 inputs)
__device__ __align__(16) float g_m1z[NROWS * ZZ];
__device__ __align__(16) float g_m2z[NROWS * ZZ];

// bf16x2-packed hi/lo operands (u32 = 2 bf16 along k)
__device__ __align__(16) unsigned g_z2hi [NROWS * 64];    // z  [4096][64]
__device__ __align__(16) unsigned g_z2lo [NROWS * 64];
__device__ __align__(16) unsigned g_w2hi [256 * 64];      // [W1;W2] [256][64]
__device__ __align__(16) unsigned g_w2lo [256 * 64];
__device__ __align__(16) unsigned g_wu2hi[128 * 128];     // Wu [128][128]
__device__ __align__(16) unsigned g_wu2lo[128 * 128];
__device__ __align__(16) unsigned g_x2hi [NROWS * 128];   // X=[z|m] [4096][128]
__device__ __align__(16) unsigned g_x2lo [NROWS * 128];

// ---------------------------------------------------------------------------
// helpers
// ---------------------------------------------------------------------------
__device__ __forceinline__ void split2(float x0, float x1,
                                       unsigned &hi, unsigned &lo)
{
    float2 v = make_float2(x0, x1);
    __nv_bfloat162 h = __float22bfloat162_rn(v);
    float2 hf = __bfloat1622float2(h);
    __nv_bfloat162 l = __float22bfloat162_rn(make_float2(v.x - hf.x, v.y - hf.y));
    hi = *reinterpret_cast<unsigned*>(&h);
    lo = *reinterpret_cast<unsigned*>(&l);
}

__device__ __forceinline__ void mma_bf16(float c[4],
    unsigned a0, unsigned a1, unsigned a2, unsigned a3,
    unsigned b0, unsigned b1)
{
    asm volatile(
        "mma.sync.aligned.m16n8k16.row.col.f32.bf16.bf16.f32 "
        "{%0,%1,%2,%3}, {%4,%5,%6,%7}, {%8,%9}, {%0,%1,%2,%3};"
        : "+f"(c[0]), "+f"(c[1]), "+f"(c[2]), "+f"(c[3])
        : "r"(a0), "r"(a1), "r"(a2), "r"(a3), "r"(b0), "r"(b1));
}

// ---------------------------------------------------------------------------
// P0: split z, [W1;W2], Wu into bf16x2 hi/lo. One float2 task per thread.
//   tasks: z 262144, Wcat 16384, Wu 16384  -> 294912 = 1152 * 256
// ---------------------------------------------------------------------------
__global__ __launch_bounds__(256) void p0_split(
    const float* __restrict__ z,
    const float* __restrict__ W1, const float* __restrict__ W2,
    const float* __restrict__ Wu)
{
    int idx = blockIdx.x * 256 + threadIdx.x;
    if (idx < NROWS * 64) {
        float2 v = ((const float2*)z)[idx];
        unsigned hi, lo; split2(v.x, v.y, hi, lo);
        g_z2hi[idx] = hi; g_z2lo[idx] = lo;
        int row = idx >> 6, kp = idx & 63;
        g_x2hi[row * 128 + kp] = hi; g_x2lo[row * 128 + kp] = lo;
    } else if (idx < NROWS * 64 + 256 * 64) {
        int i = idx - NROWS * 64;
        int n = i >> 6, kp = i & 63;
        const float* Wr = (n < 128) ? (W1 + n * 128) : (W2 + (n - 128) * 128);
        unsigned hi, lo; split2(Wr[2 * kp], Wr[2 * kp + 1], hi, lo);
        g_w2hi[i] = hi; g_w2lo[i] = lo;
    } else if (idx < NROWS * 64 + 256 * 64 + 128 * 128) {
        int i = idx - NROWS * 64 - 256 * 64;
        int h = i >> 7, kp = i & 127;
        unsigned hi, lo; split2(Wu[h * 256 + 2 * kp], Wu[h * 256 + 2 * kp + 1], hi, lo);
        g_wu2hi[i] = hi; g_wu2lo[i] = lo;
    }
}

// ---------------------------------------------------------------------------
// K1': [m1z | m2z] = z @ [W1;W2]^T + bias   via 3-pass bf16 split mma.
// grid (64 row-blocks, 8 n-bands of 32), 256 threads = 8 warps (4m x 2n).
// Warp tile 16x16 = 2 ntiles of m16n8k16; block tile 64m x 32n.
// 4096 warps total (~27/SM) — latency hidden by occupancy, no smem/syncs.
// ---------------------------------------------------------------------------
__global__ __launch_bounds__(256) void k1_mma(
    const float* __restrict__ b1, const float* __restrict__ b2)
{
    const int lane = threadIdx.x & 31;
    const int wid  = threadIdx.x >> 5;
    const int wm   = wid >> 1, wn = wid & 1;
    const int g    = lane >> 2, t = lane & 3;
    const int row0 = blockIdx.x * 64 + wm * 16;
    const int n0   = blockIdx.y * 32 + wn * 16;

    float c[2][4];
#pragma unroll
    for (int nt = 0; nt < 2; nt++)
#pragma unroll
        for (int q = 0; q < 4; q++) c[nt][q] = 0.f;

#pragma unroll
    for (int ks = 0; ks < 8; ks++) {
        const int kp0 = ks * 8;
        const int ra = (row0 + g) * 64 + kp0 + t;
        const int rb = (row0 + g + 8) * 64 + kp0 + t;
        unsigned ah0 = g_z2hi[ra],     ah1 = g_z2hi[rb];
        unsigned ah2 = g_z2hi[ra + 4], ah3 = g_z2hi[rb + 4];
        unsigned al0 = g_z2lo[ra],     al1 = g_z2lo[rb];
        unsigned al2 = g_z2lo[ra + 4], al3 = g_z2lo[rb + 4];

        unsigned bh[2][2], bl[2][2];
#pragma unroll
        for (int nt = 0; nt < 2; nt++) {
            int nb = (n0 + nt * 8 + g) * 64 + kp0 + t;
            bh[nt][0] = g_w2hi[nb]; bh[nt][1] = g_w2hi[nb + 4];
            bl[nt][0] = g_w2lo[nb]; bl[nt][1] = g_w2lo[nb + 4];
        }
#pragma unroll
        for (int nt = 0; nt < 2; nt++) {
            mma_bf16(c[nt], ah0, ah1, ah2, ah3, bh[nt][0], bh[nt][1]);
            mma_bf16(c[nt], ah0, ah1, ah2, ah3, bl[nt][0], bl[nt][1]);
            mma_bf16(c[nt], al0, al1, al2, al3, bh[nt][0], bh[nt][1]);
        }
    }

    const bool second = (n0 >= 128);
    float* __restrict__ dst = second ? g_m2z : g_m1z;
    const float* __restrict__ bias = second ? b2 : b1;
    const int nbase = second ? (n0 - 128) : n0;

#pragma unroll
    for (int nt = 0; nt < 2; nt++) {
        int n = nbase + nt * 8 + 2 * t;
        float bv0 = bias[n], bv1 = bias[n + 1];
        int r = row0 + g;
        dst[r * 128 + n]           = c[nt][0] + bv0;
        dst[r * 128 + n + 1]       = c[nt][1] + bv1;
        dst[(r + 8) * 128 + n]     = c[nt][2] + bv0;
        dst[(r + 8) * 128 + n + 1] = c[nt][3] + bv1;
    }
}

// ---------------------------------------------------------------------------
// K2: relu(m1z[b,i,c] + max_{j:P[b,j,i]!=0} m2z[b,j,c]); writes bf16 hi/lo
// message half of X. grid (16 i-tiles, 16 batches), 256 threads.
//   c4 = tid&31 -> 4 channels ; sg = tid>>5 -> i = i0+sg*2+{0,1}
// ---------------------------------------------------------------------------
__global__ __launch_bounds__(256) void k2_maskmax(const int* __restrict__ P)
{
    __shared__ unsigned smask[256];   // low 16 bits used

    const int tid  = threadIdx.x;
    const int b    = blockIdx.y;
    const int i0   = blockIdx.x * 16;
    const int lane = tid & 31;
    const int wrp  = tid >> 5;

    for (int jp = wrp; jp < 128; jp += 8) {
        int j  = 2 * jp + (lane >> 4);
        int io = lane & 15;
        int v  = P[((b * 256 + j) * 256) + i0 + io];
        unsigned word = __ballot_sync(0xffffffffu, v != 0);
        if (lane == 0) {
            smask[2 * jp]     = word & 0xffffu;
            smask[2 * jp + 1] = word >> 16;
        }
    }
    __syncthreads();

    const int c4 = tid & 31;
    const int sg = tid >> 5;

    float4 mx0 = make_float4(-3.0e38f, -3.0e38f, -3.0e38f, -3.0e38f);
    float4 mx1 = mx0;

    const float4* m2 = (const float4*)g_m2z + (size_t)b * 256 * 32;

#pragma unroll 8
    for (int j = 0; j < 256; j++) {
        float4 v = m2[j * 32 + c4];
        unsigned mw = smask[j] >> (sg * 2);
        if (mw & 1u) {
            mx0.x = fmaxf(mx0.x, v.x); mx0.y = fmaxf(mx0.y, v.y);
            mx0.z = fmaxf(mx0.z, v.z); mx0.w = fmaxf(mx0.w, v.w);
        }
        if (mw & 2u) {
            mx1.x = fmaxf(mx1.x, v.x); mx1.y = fmaxf(mx1.y, v.y);
            mx1.z = fmaxf(mx1.z, v.z); mx1.w = fmaxf(mx1.w, v.w);
        }
    }

    const float4* m1 = (const float4*)g_m1z + (size_t)b * 256 * 32;

#pragma unroll
    for (int s = 0; s < 2; s++) {
        int i = i0 + sg * 2 + s;
        float4 mxv = s ? mx1 : mx0;
        float4 a = m1[i * 32 + c4];
        float4 o;
        o.x = fmaxf(a.x + mxv.x, 0.f); o.y = fmaxf(a.y + mxv.y, 0.f);
        o.z = fmaxf(a.z + mxv.z, 0.f); o.w = fmaxf(a.w + mxv.w, 0.f);

        int grow = b * 256 + i;
        unsigned h0, l0, h1, l1;
        split2(o.x, o.y, h0, l0);
        split2(o.z, o.w, h1, l1);
        int base = grow * 128 + 64 + 2 * c4;
        g_x2hi[base]     = h0; g_x2hi[base + 1] = h1;
        g_x2lo[base]     = l0; g_x2lo[base + 1] = l1;
    }
}

// ---------------------------------------------------------------------------
// K3': out = relu(X @ Wu^T + bu), X = [z | m] (pre-split bf16 hi/lo), K=256.
// grid (64 row-blocks, 4 n-bands of 32), 256 threads = 8 warps (4m x 2n).
// Warp tile 16x16; block tile 64m x 32n. 2048 warps (~14/SM). 16 ksteps.
// ---------------------------------------------------------------------------
__global__ __launch_bounds__(256) void k3_mma(
    const float* __restrict__ bu, float* __restrict__ out)
{
    const int lane = threadIdx.x & 31;
    const int wid  = threadIdx.x >> 5;
    const int wm   = wid >> 1, wn = wid & 1;
    const int g    = lane >> 2, t = lane & 3;
    const int row0 = blockIdx.x * 64 + wm * 16;
    const int n0   = blockIdx.y * 32 + wn * 16;

    float c[2][4];
#pragma unroll
    for (int nt = 0; nt < 2; nt++)
#pragma unroll
        for (int q = 0; q < 4; q++) c[nt][q] = 0.f;

#pragma unroll
    for (int ks = 0; ks < 16; ks++) {
        const int kp0 = ks * 8;
        const int ra = (row0 + g) * 128 + kp0 + t;
        const int rb = (row0 + g + 8) * 128 + kp0 + t;
        unsigned ah0 = g_x2hi[ra],     ah1 = g_x2hi[rb];
        unsigned ah2 = g_x2hi[ra + 4], ah3 = g_x2hi[rb + 4];
        unsigned al0 = g_x2lo[ra],     al1 = g_x2lo[rb];
        unsigned al2 = g_x2lo[ra + 4], al3 = g_x2lo[rb + 4];

        unsigned bh[2][2], bl[2][2];
#pragma unroll
        for (int nt = 0; nt < 2; nt++) {
            int nb = (n0 + nt * 8 + g) * 128 + kp0 + t;
            bh[nt][0] = g_wu2hi[nb]; bh[nt][1] = g_wu2hi[nb + 4];
            bl[nt][0] = g_wu2lo[nb]; bl[nt][1] = g_wu2lo[nb + 4];
        }
#pragma unroll
        for (int nt = 0; nt < 2; nt++) {
            mma_bf16(c[nt], ah0, ah1, ah2, ah3, bh[nt][0], bh[nt][1]);
            mma_bf16(c[nt], ah0, ah1, ah2, ah3, bl[nt][0], bl[nt][1]);
            mma_bf16(c[nt], al0, al1, al2, al3, bh[nt][0], bh[nt][1]);
        }
    }

#pragma unroll
    for (int nt = 0; nt < 2; nt++) {
        int n = n0 + nt * 8 + 2 * t;
        float bv0 = bu[n], bv1 = bu[n + 1];
        int r = row0 + g;
        out[r * 128 + n]           = fmaxf(c[nt][0] + bv0, 0.f);
        out[r * 128 + n + 1]       = fmaxf(c[nt][1] + bv1, 0.f);
        out[(r + 8) * 128 + n]     = fmaxf(c[nt][2] + bv0, 0.f);
        out[(r + 8) * 128 + n + 1] = fmaxf(c[nt][3] + bv1, 0.f);
    }
}

// ---------------------------------------------------------------------------
// Launch. Inputs (metadata order): z, P, W1, b1, W2, b2, Wu, bu.
// ---------------------------------------------------------------------------
extern "C" void kernel_launch(void* const* d_in, const int* in_sizes, int n_in,
                              void* d_out, int out_size)
{
    const float* z  = (const float*)d_in[0];
    const int*   P  = (const int*)  d_in[1];
    const float* W1 = (const float*)d_in[2];
    const float* b1 = (const float*)d_in[3];
    const float* W2 = (const float*)d_in[4];
    const float* b2 = (const float*)d_in[5];
    const float* Wu = (const float*)d_in[6];
    const float* bu = (const float*)d_in[7];
    float* out = (float*)d_out;

    p0_split<<<1152, 256>>>(z, W1, W2, Wu);

    dim3 g1(64, 8);
    k1_mma<<<g1, 256>>>(b1, b2);

    dim3 g2(16, 16);
    k2_maskmax<<<g2, 256>>>(P);

    dim3 g3(64, 4);
    k3_mma<<<g3, 256>>>(bu, out);
}

// round 13
// speedup vs baseline: 1.3341x; 1.3341x over previous
#include <cuda_runtime.h>
#include <cuda_bf16.h>
#include <cstdint>

// Problem constants
#define BB 16
#define KK 256
#define ZZ 128
#define HH 128
#define NROWS (BB * KK)   // 4096

// fp32 scratch (K2 inputs)
__device__ __align__(16) float g_m1z[NROWS * ZZ];
__device__ __align__(16) float g_m2z[NROWS * ZZ];

// mma-fragment-layout operand storage (u32 = bf16x2 along k)
// A tile (16 rows x 8 kpairs) = 256 u32: [hi 32 lanes x 4 regs | lo ...]
// B tile ( 8 cols x 8 kpairs) = 128 u32: [hi 32 lanes x 2 regs | lo ...]
__device__ __align__(16) unsigned g_zA [256 * 8  * 256];  // z   A-frags (2 MB)
__device__ __align__(16) unsigned g_xA [256 * 16 * 256];  // X   A-frags (4 MB)
__device__ __align__(16) unsigned g_wB [32  * 8  * 128];  // [W1;W2] B-frags
__device__ __align__(16) unsigned g_wuB[16  * 16 * 128];  // Wu  B-frags

// ---------------------------------------------------------------------------
// helpers
// ---------------------------------------------------------------------------
__device__ __forceinline__ void split2(float x0, float x1,
                                       unsigned &hi, unsigned &lo)
{
    float2 v = make_float2(x0, x1);
    __nv_bfloat162 h = __float22bfloat162_rn(v);
    float2 hf = __bfloat1622float2(h);
    __nv_bfloat162 l = __float22bfloat162_rn(make_float2(v.x - hf.x, v.y - hf.y));
    hi = *reinterpret_cast<unsigned*>(&h);
    lo = *reinterpret_cast<unsigned*>(&l);
}

// address (hi element) of A-operand (row, kpair) in fragment layout
__device__ __forceinline__ int a_addr(int row, int kp, int nkt)
{
    int mt = row >> 4, r = row & 15;
    int kt = kp >> 3,  kq = kp & 7;
    int lane = ((r & 7) << 2) | (kq & 3);
    int reg  = (r >> 3) | ((kq >> 2) << 1);
    return (mt * nkt + kt) * 256 + lane * 4 + reg;   // lo at +128
}

// address (hi element) of B-operand (n, kpair) in fragment layout
__device__ __forceinline__ int b_addr(int n, int kp, int nkt)
{
    int nt = n >> 3, gn = n & 7;
    int kt = kp >> 3, kq = kp & 7;
    int lane = (gn << 2) | (kq & 3);
    int reg  = kq >> 2;
    return (nt * nkt + kt) * 128 + lane * 2 + reg;   // lo at +64
}

__device__ __forceinline__ void mma_bf16(float c[4],
    unsigned a0, unsigned a1, unsigned a2, unsigned a3,
    unsigned b0, unsigned b1)
{
    asm volatile(
        "mma.sync.aligned.m16n8k16.row.col.f32.bf16.bf16.f32 "
        "{%0,%1,%2,%3}, {%4,%5,%6,%7}, {%8,%9}, {%0,%1,%2,%3};"
        : "+f"(c[0]), "+f"(c[1]), "+f"(c[2]), "+f"(c[3])
        : "r"(a0), "r"(a1), "r"(a2), "r"(a3), "r"(b0), "r"(b1));
}

// ---------------------------------------------------------------------------
// P0: split z, [W1;W2], Wu into bf16 hi/lo fragment layouts.
//   tasks: z 262144, Wcat 16384, Wu 16384  -> 294912 = 1152 * 256
// ---------------------------------------------------------------------------
__global__ __launch_bounds__(256) void p0_split(
    const float* __restrict__ z,
    const float* __restrict__ W1, const float* __restrict__ W2,
    const float* __restrict__ Wu)
{
    int idx = blockIdx.x * 256 + threadIdx.x;
    if (idx < NROWS * 64) {
        float2 v = ((const float2*)z)[idx];
        unsigned hi, lo; split2(v.x, v.y, hi, lo);
        int row = idx >> 6, kp = idx & 63;
        int a1 = a_addr(row, kp, 8);
        g_zA[a1] = hi; g_zA[a1 + 128] = lo;
        int a2 = a_addr(row, kp, 16);
        g_xA[a2] = hi; g_xA[a2 + 128] = lo;
    } else if (idx < NROWS * 64 + 256 * 64) {
        int i = idx - NROWS * 64;
        int n = i >> 6, kp = i & 63;
        const float* Wr = (n < 128) ? (W1 + n * 128) : (W2 + (n - 128) * 128);
        unsigned hi, lo; split2(Wr[2 * kp], Wr[2 * kp + 1], hi, lo);
        int b = b_addr(n, kp, 8);
        g_wB[b] = hi; g_wB[b + 64] = lo;
    } else if (idx < NROWS * 64 + 256 * 64 + 128 * 128) {
        int i = idx - NROWS * 64 - 256 * 64;
        int h = i >> 7, kp = i & 127;
        unsigned hi, lo; split2(Wu[h * 256 + 2 * kp], Wu[h * 256 + 2 * kp + 1], hi, lo);
        int b = b_addr(h, kp, 16);
        g_wuB[b] = hi; g_wuB[b + 64] = lo;
    }
}

// ---------------------------------------------------------------------------
// K1': [m1z | m2z] = z @ [W1;W2]^T + bias  (3-pass bf16 split mma)
// grid (64, 8), 128 threads = 4 warps (2m x 2n). Warp tile 32m x 16n
// (2 mtiles x 2 ntiles), block tile 64m x 32n, K = 128 (8 ksteps).
// All fragment loads are coalesced LDG.128 / LDG.64 from fragment layout.
// ---------------------------------------------------------------------------
__global__ __launch_bounds__(128) void k1_mma(
    const float* __restrict__ b1, const float* __restrict__ b2)
{
    const int lane = threadIdx.x & 31;
    const int wid  = threadIdx.x >> 5;
    const int wm   = wid >> 1, wn = wid & 1;
    const int g    = lane >> 2, t = lane & 3;
    const int row0 = blockIdx.x * 64 + wm * 32;
    const int n0   = blockIdx.y * 32 + wn * 16;
    const int mtb  = row0 >> 4;   // first mtile
    const int ntb  = n0 >> 3;     // first ntile

    float c[2][2][4];
#pragma unroll
    for (int mt = 0; mt < 2; mt++)
#pragma unroll
        for (int nt = 0; nt < 2; nt++)
#pragma unroll
            for (int q = 0; q < 4; q++) c[mt][nt][q] = 0.f;

#pragma unroll
    for (int ks = 0; ks < 8; ks++) {
        uint4 ah[2], al[2];
        uint2 bh[2], bl[2];
#pragma unroll
        for (int mt = 0; mt < 2; mt++) {
            const unsigned* pa = &g_zA[((mtb + mt) * 8 + ks) * 256 + lane * 4];
            ah[mt] = *(const uint4*)pa;
            al[mt] = *(const uint4*)(pa + 128);
        }
#pragma unroll
        for (int nt = 0; nt < 2; nt++) {
            const unsigned* pb = &g_wB[((ntb + nt) * 8 + ks) * 128 + lane * 2];
            bh[nt] = *(const uint2*)pb;
            bl[nt] = *(const uint2*)(pb + 64);
        }
#pragma unroll
        for (int mt = 0; mt < 2; mt++)
#pragma unroll
            for (int nt = 0; nt < 2; nt++) {
                mma_bf16(c[mt][nt], ah[mt].x, ah[mt].y, ah[mt].z, ah[mt].w,
                         bh[nt].x, bh[nt].y);
                mma_bf16(c[mt][nt], ah[mt].x, ah[mt].y, ah[mt].z, ah[mt].w,
                         bl[nt].x, bl[nt].y);
                mma_bf16(c[mt][nt], al[mt].x, al[mt].y, al[mt].z, al[mt].w,
                         bh[nt].x, bh[nt].y);
            }
    }

    const bool second = (n0 >= 128);
    float* __restrict__ dst = second ? g_m2z : g_m1z;
    const float* __restrict__ bias = second ? b2 : b1;
    const int nbase = second ? (n0 - 128) : n0;

#pragma unroll
    for (int mt = 0; mt < 2; mt++)
#pragma unroll
        for (int nt = 0; nt < 2; nt++) {
            int n = nbase + nt * 8 + 2 * t;
            float bv0 = bias[n], bv1 = bias[n + 1];
            int r = row0 + mt * 16 + g;
            dst[r * 128 + n]           = c[mt][nt][0] + bv0;
            dst[r * 128 + n + 1]       = c[mt][nt][1] + bv1;
            dst[(r + 8) * 128 + n]     = c[mt][nt][2] + bv0;
            dst[(r + 8) * 128 + n + 1] = c[mt][nt][3] + bv1;
        }
}

// ---------------------------------------------------------------------------
// K2: relu(m1z[b,i,c] + max_{j:P[b,j,i]!=0} m2z[b,j,c]); writes bf16 hi/lo
// message half of X in fragment layout. grid (16 i-tiles, 16 batches),
// 256 threads. c4 = tid&31 -> 4 channels ; sg = tid>>5 -> i = i0+sg*2+{0,1}
// ---------------------------------------------------------------------------
__global__ __launch_bounds__(256) void k2_maskmax(const int* __restrict__ P)
{
    __shared__ unsigned smask[256];   // low 16 bits used

    const int tid  = threadIdx.x;
    const int b    = blockIdx.y;
    const int i0   = blockIdx.x * 16;
    const int lane = tid & 31;
    const int wrp  = tid >> 5;

    for (int jp = wrp; jp < 128; jp += 8) {
        int j  = 2 * jp + (lane >> 4);
        int io = lane & 15;
        int v  = P[((b * 256 + j) * 256) + i0 + io];
        unsigned word = __ballot_sync(0xffffffffu, v != 0);
        if (lane == 0) {
            smask[2 * jp]     = word & 0xffffu;
            smask[2 * jp + 1] = word >> 16;
        }
    }
    __syncthreads();

    const int c4 = tid & 31;
    const int sg = tid >> 5;

    float4 mx0 = make_float4(-3.0e38f, -3.0e38f, -3.0e38f, -3.0e38f);
    float4 mx1 = mx0;

    const float4* m2 = (const float4*)g_m2z + (size_t)b * 256 * 32;

#pragma unroll 8
    for (int j = 0; j < 256; j++) {
        float4 v = m2[j * 32 + c4];
        unsigned mw = smask[j] >> (sg * 2);
        if (mw & 1u) {
            mx0.x = fmaxf(mx0.x, v.x); mx0.y = fmaxf(mx0.y, v.y);
            mx0.z = fmaxf(mx0.z, v.z); mx0.w = fmaxf(mx0.w, v.w);
        }
        if (mw & 2u) {
            mx1.x = fmaxf(mx1.x, v.x); mx1.y = fmaxf(mx1.y, v.y);
            mx1.z = fmaxf(mx1.z, v.z); mx1.w = fmaxf(mx1.w, v.w);
        }
    }

    const float4* m1 = (const float4*)g_m1z + (size_t)b * 256 * 32;

#pragma unroll
    for (int s = 0; s < 2; s++) {
        int i = i0 + sg * 2 + s;
        float4 mxv = s ? mx1 : mx0;
        float4 a = m1[i * 32 + c4];
        float4 o;
        o.x = fmaxf(a.x + mxv.x, 0.f); o.y = fmaxf(a.y + mxv.y, 0.f);
        o.z = fmaxf(a.z + mxv.z, 0.f); o.w = fmaxf(a.w + mxv.w, 0.f);

        int grow = b * 256 + i;
        unsigned h0, l0, h1, l1;
        split2(o.x, o.y, h0, l0);
        split2(o.z, o.w, h1, l1);
        int kp = 64 + 2 * c4;            // message kpairs
        int a0 = a_addr(grow, kp, 16);
        int a1 = a_addr(grow, kp + 1, 16);
        g_xA[a0] = h0; g_xA[a0 + 128] = l0;
        g_xA[a1] = h1; g_xA[a1 + 128] = l1;
    }
}

// ---------------------------------------------------------------------------
// K3': out = relu(X @ Wu^T + bu), X = [z | m] in fragment layout, K = 256
// (16 ksteps). grid (64, 4), 128 threads = 4 warps, warp tile 32m x 16n.
// ---------------------------------------------------------------------------
__global__ __launch_bounds__(128) void k3_mma(
    const float* __restrict__ bu, float* __restrict__ out)
{
    const int lane = threadIdx.x & 31;
    const int wid  = threadIdx.x >> 5;
    const int wm   = wid >> 1, wn = wid & 1;
    const int g    = lane >> 2, t = lane & 3;
    const int row0 = blockIdx.x * 64 + wm * 32;
    const int n0   = blockIdx.y * 32 + wn * 16;
    const int mtb  = row0 >> 4;
    const int ntb  = n0 >> 3;

    float c[2][2][4];
#pragma unroll
    for (int mt = 0; mt < 2; mt++)
#pragma unroll
        for (int nt = 0; nt < 2; nt++)
#pragma unroll
            for (int q = 0; q < 4; q++) c[mt][nt][q] = 0.f;

#pragma unroll 8
    for (int ks = 0; ks < 16; ks++) {
        uint4 ah[2], al[2];
        uint2 bh[2], bl[2];
#pragma unroll
        for (int mt = 0; mt < 2; mt++) {
            const unsigned* pa = &g_xA[((mtb + mt) * 16 + ks) * 256 + lane * 4];
            ah[mt] = *(const uint4*)pa;
            al[mt] = *(const uint4*)(pa + 128);
        }
#pragma unroll
        for (int nt = 0; nt < 2; nt++) {
            const unsigned* pb = &g_wuB[((ntb + nt) * 16 + ks) * 128 + lane * 2];
            bh[nt] = *(const uint2*)pb;
            bl[nt] = *(const uint2*)(pb + 64);
        }
#pragma unroll
        for (int mt = 0; mt < 2; mt++)
#pragma unroll
            for (int nt = 0; nt < 2; nt++) {
                mma_bf16(c[mt][nt], ah[mt].x, ah[mt].y, ah[mt].z, ah[mt].w,
                         bh[nt].x, bh[nt].y);
                mma_bf16(c[mt][nt], ah[mt].x, ah[mt].y, ah[mt].z, ah[mt].w,
                         bl[nt].x, bl[nt].y);
                mma_bf16(c[mt][nt], al[mt].x, al[mt].y, al[mt].z, al[mt].w,
                         bh[nt].x, bh[nt].y);
            }
    }

#pragma unroll
    for (int mt = 0; mt < 2; mt++)
#pragma unroll
        for (int nt = 0; nt < 2; nt++) {
            int n = n0 + nt * 8 + 2 * t;
            float bv0 = bu[n], bv1 = bu[n + 1];
            int r = row0 + mt * 16 + g;
            out[r * 128 + n]           = fmaxf(c[mt][nt][0] + bv0, 0.f);
            out[r * 128 + n + 1]       = fmaxf(c[mt][nt][1] + bv1, 0.f);
            out[(r + 8) * 128 + n]     = fmaxf(c[mt][nt][2] + bv0, 0.f);
            out[(r + 8) * 128 + n + 1] = fmaxf(c[mt][nt][3] + bv1, 0.f);
        }
}

// ---------------------------------------------------------------------------
// Launch. Inputs (metadata order): z, P, W1, b1, W2, b2, Wu, bu.
// ---------------------------------------------------------------------------
extern "C" void kernel_launch(void* const* d_in, const int* in_sizes, int n_in,
                              void* d_out, int out_size)
{
    const float* z  = (const float*)d_in[0];
    const int*   P  = (const int*)  d_in[1];
    const float* W1 = (const float*)d_in[2];
    const float* b1 = (const float*)d_in[3];
    const float* W2 = (const float*)d_in[4];
    const float* b2 = (const float*)d_in[5];
    const float* Wu = (const float*)d_in[6];
    const float* bu = (const float*)d_in[7];
    float* out = (float*)d_out;

    p0_split<<<1152, 256>>>(z, W1, W2, Wu);

    dim3 g1(64, 8);
    k1_mma<<<g1, 128>>>(b1, b2);

    dim3 g2(16, 16);
    k2_maskmax<<<g2, 256>>>(P);

    dim3 g3(64, 4);
    k3_mma<<<g3, 128>>>(bu, out);
}

// round 14
// speedup vs baseline: 1.5464x; 1.1591x over previous
#include <cuda_runtime.h>
#include <cuda_bf16.h>
#include <cstdint>

// Problem constants
#define BB 16
#define KK 256
#define ZZ 128
#define HH 128
#define NROWS (BB * KK)   // 4096

// fp32 scratch (K2 inputs)
__device__ __align__(16) float g_m1z[NROWS * ZZ];
__device__ __align__(16) float g_m2z[NROWS * ZZ];

// mma-fragment-layout operand storage (u32 = bf16x2 along k)
// A tile (16 rows x 8 kpairs) = 256 u32: [hi 32 lanes x 4 regs | lo ...]
// B tile ( 8 cols x 8 kpairs) = 128 u32: [hi 32 lanes x 2 regs | lo ...]
__device__ __align__(16) unsigned g_zA [256 * 8  * 256];  // z   A-frags (2 MB)
__device__ __align__(16) unsigned g_xA [256 * 16 * 256];  // X   A-frags (4 MB)
__device__ __align__(16) unsigned g_wB [32  * 8  * 128];  // [W1;W2] B-frags
__device__ __align__(16) unsigned g_wuB[16  * 16 * 128];  // Wu  B-frags

// ---------------------------------------------------------------------------
// helpers
// ---------------------------------------------------------------------------
__device__ __forceinline__ void split2(float x0, float x1,
                                       unsigned &hi, unsigned &lo)
{
    float2 v = make_float2(x0, x1);
    __nv_bfloat162 h = __float22bfloat162_rn(v);
    float2 hf = __bfloat1622float2(h);
    __nv_bfloat162 l = __float22bfloat162_rn(make_float2(v.x - hf.x, v.y - hf.y));
    hi = *reinterpret_cast<unsigned*>(&h);
    lo = *reinterpret_cast<unsigned*>(&l);
}

// address (hi element) of A-operand (row, kpair) in fragment layout
__device__ __forceinline__ int a_addr(int row, int kp, int nkt)
{
    int mt = row >> 4, r = row & 15;
    int kt = kp >> 3,  kq = kp & 7;
    int lane = ((r & 7) << 2) | (kq & 3);
    int reg  = (r >> 3) | ((kq >> 2) << 1);
    return (mt * nkt + kt) * 256 + lane * 4 + reg;   // lo at +128
}

// address (hi element) of B-operand (n, kpair) in fragment layout
__device__ __forceinline__ int b_addr(int n, int kp, int nkt)
{
    int nt = n >> 3, gn = n & 7;
    int kt = kp >> 3, kq = kp & 7;
    int lane = (gn << 2) | (kq & 3);
    int reg  = kq >> 2;
    return (nt * nkt + kt) * 128 + lane * 2 + reg;   // lo at +64
}

__device__ __forceinline__ void mma_bf16(float c[4],
    unsigned a0, unsigned a1, unsigned a2, unsigned a3,
    unsigned b0, unsigned b1)
{
    asm volatile(
        "mma.sync.aligned.m16n8k16.row.col.f32.bf16.bf16.f32 "
        "{%0,%1,%2,%3}, {%4,%5,%6,%7}, {%8,%9}, {%0,%1,%2,%3};"
        : "+f"(c[0]), "+f"(c[1]), "+f"(c[2]), "+f"(c[3])
        : "r"(a0), "r"(a1), "r"(a2), "r"(a3), "r"(b0), "r"(b1));
}

// ---------------------------------------------------------------------------
// P0: split z, [W1;W2], Wu into bf16 hi/lo fragment layouts.
//   tasks: z 262144, Wcat 16384, Wu 16384  -> 294912 = 1152 * 256
// ---------------------------------------------------------------------------
__global__ __launch_bounds__(256) void p0_split(
    const float* __restrict__ z,
    const float* __restrict__ W1, const float* __restrict__ W2,
    const float* __restrict__ Wu)
{
    int idx = blockIdx.x * 256 + threadIdx.x;
    if (idx < NROWS * 64) {
        float2 v = ((const float2*)z)[idx];
        unsigned hi, lo; split2(v.x, v.y, hi, lo);
        int row = idx >> 6, kp = idx & 63;
        int a1 = a_addr(row, kp, 8);
        g_zA[a1] = hi; g_zA[a1 + 128] = lo;
        int a2 = a_addr(row, kp, 16);
        g_xA[a2] = hi; g_xA[a2 + 128] = lo;
    } else if (idx < NROWS * 64 + 256 * 64) {
        int i = idx - NROWS * 64;
        int n = i >> 6, kp = i & 63;
        const float* Wr = (n < 128) ? (W1 + n * 128) : (W2 + (n - 128) * 128);
        unsigned hi, lo; split2(Wr[2 * kp], Wr[2 * kp + 1], hi, lo);
        int b = b_addr(n, kp, 8);
        g_wB[b] = hi; g_wB[b + 64] = lo;
    } else if (idx < NROWS * 64 + 256 * 64 + 128 * 128) {
        int i = idx - NROWS * 64 - 256 * 64;
        int h = i >> 7, kp = i & 127;
        unsigned hi, lo; split2(Wu[h * 256 + 2 * kp], Wu[h * 256 + 2 * kp + 1], hi, lo);
        int b = b_addr(h, kp, 16);
        g_wuB[b] = hi; g_wuB[b + 64] = lo;
    }
}

// ---------------------------------------------------------------------------
// K1': [m1z | m2z] = z @ [W1;W2]^T + bias  (3-pass bf16 split mma)
// grid (64, 8), 256 threads = 8 warps (4m x 2n). Warp tile 16m x 16n,
// block tile 64m x 32n, K = 128 (8 ksteps). 4096 warps (~27/SM).
// Software-pipelined: kstep+1 fragments prefetched into a second register
// buffer before the 6 mmas of kstep -> one exposed L2 trip total.
// ---------------------------------------------------------------------------
__global__ __launch_bounds__(256) void k1_mma(
    const float* __restrict__ b1, const float* __restrict__ b2)
{
    const int lane = threadIdx.x & 31;
    const int wid  = threadIdx.x >> 5;
    const int wm   = wid >> 1, wn = wid & 1;
    const int g    = lane >> 2, t = lane & 3;
    const int row0 = blockIdx.x * 64 + wm * 16;
    const int n0   = blockIdx.y * 32 + wn * 16;
    const int mt   = row0 >> 4;
    const int ntb  = n0 >> 3;

    const unsigned* pa  = &g_zA[(mt * 8) * 256 + lane * 4];
    const unsigned* pb0 = &g_wB[(ntb * 8) * 128 + lane * 2];
    const unsigned* pb1 = &g_wB[((ntb + 1) * 8) * 128 + lane * 2];

    float c[2][4];
#pragma unroll
    for (int nt = 0; nt < 2; nt++)
#pragma unroll
        for (int q = 0; q < 4; q++) c[nt][q] = 0.f;

    uint4 ah  = *(const uint4*)pa;
    uint4 al  = *(const uint4*)(pa + 128);
    uint2 bh0 = *(const uint2*)pb0, bl0 = *(const uint2*)(pb0 + 64);
    uint2 bh1 = *(const uint2*)pb1, bl1 = *(const uint2*)(pb1 + 64);

#pragma unroll
    for (int ks = 0; ks < 8; ks++) {
        uint4 nah, nal; uint2 nbh0, nbl0, nbh1, nbl1;
        if (ks < 7) {
            const unsigned* qa = pa + (ks + 1) * 256;
            nah = *(const uint4*)qa;  nal = *(const uint4*)(qa + 128);
            const unsigned* q0 = pb0 + (ks + 1) * 128;
            nbh0 = *(const uint2*)q0; nbl0 = *(const uint2*)(q0 + 64);
            const unsigned* q1 = pb1 + (ks + 1) * 128;
            nbh1 = *(const uint2*)q1; nbl1 = *(const uint2*)(q1 + 64);
        }
        mma_bf16(c[0], ah.x, ah.y, ah.z, ah.w, bh0.x, bh0.y);
        mma_bf16(c[0], ah.x, ah.y, ah.z, ah.w, bl0.x, bl0.y);
        mma_bf16(c[0], al.x, al.y, al.z, al.w, bh0.x, bh0.y);
        mma_bf16(c[1], ah.x, ah.y, ah.z, ah.w, bh1.x, bh1.y);
        mma_bf16(c[1], ah.x, ah.y, ah.z, ah.w, bl1.x, bl1.y);
        mma_bf16(c[1], al.x, al.y, al.z, al.w, bh1.x, bh1.y);
        if (ks < 7) {
            ah = nah; al = nal;
            bh0 = nbh0; bl0 = nbl0; bh1 = nbh1; bl1 = nbl1;
        }
    }

    const bool second = (n0 >= 128);
    float* __restrict__ dst = second ? g_m2z : g_m1z;
    const float* __restrict__ bias = second ? b2 : b1;
    const int nbase = second ? (n0 - 128) : n0;

#pragma unroll
    for (int nt = 0; nt < 2; nt++) {
        int n = nbase + nt * 8 + 2 * t;
        float bv0 = bias[n], bv1 = bias[n + 1];
        int r = row0 + g;
        dst[r * 128 + n]           = c[nt][0] + bv0;
        dst[r * 128 + n + 1]       = c[nt][1] + bv1;
        dst[(r + 8) * 128 + n]     = c[nt][2] + bv0;
        dst[(r + 8) * 128 + n + 1] = c[nt][3] + bv1;
    }
}

// ---------------------------------------------------------------------------
// K2: relu(m1z[b,i,c] + max_{j:P[b,j,i]!=0} m2z[b,j,c]); writes bf16 hi/lo
// message half of X in fragment layout. grid (16 i-tiles, 16 batches),
// 256 threads. c4 = tid&31 -> 4 channels ; sg = tid>>5 -> i = i0+sg*2+{0,1}
// ---------------------------------------------------------------------------
__global__ __launch_bounds__(256) void k2_maskmax(const int* __restrict__ P)
{
    __shared__ unsigned smask[256];   // low 16 bits used

    const int tid  = threadIdx.x;
    const int b    = blockIdx.y;
    const int i0   = blockIdx.x * 16;
    const int lane = tid & 31;
    const int wrp  = tid >> 5;

    for (int jp = wrp; jp < 128; jp += 8) {
        int j  = 2 * jp + (lane >> 4);
        int io = lane & 15;
        int v  = P[((b * 256 + j) * 256) + i0 + io];
        unsigned word = __ballot_sync(0xffffffffu, v != 0);
        if (lane == 0) {
            smask[2 * jp]     = word & 0xffffu;
            smask[2 * jp + 1] = word >> 16;
        }
    }
    __syncthreads();

    const int c4 = tid & 31;
    const int sg = tid >> 5;

    float4 mx0 = make_float4(-3.0e38f, -3.0e38f, -3.0e38f, -3.0e38f);
    float4 mx1 = mx0;

    const float4* m2 = (const float4*)g_m2z + (size_t)b * 256 * 32;

#pragma unroll 8
    for (int j = 0; j < 256; j++) {
        float4 v = m2[j * 32 + c4];
        unsigned mw = smask[j] >> (sg * 2);
        if (mw & 1u) {
            mx0.x = fmaxf(mx0.x, v.x); mx0.y = fmaxf(mx0.y, v.y);
            mx0.z = fmaxf(mx0.z, v.z); mx0.w = fmaxf(mx0.w, v.w);
        }
        if (mw & 2u) {
            mx1.x = fmaxf(mx1.x, v.x); mx1.y = fmaxf(mx1.y, v.y);
            mx1.z = fmaxf(mx1.z, v.z); mx1.w = fmaxf(mx1.w, v.w);
        }
    }

    const float4* m1 = (const float4*)g_m1z + (size_t)b * 256 * 32;

#pragma unroll
    for (int s = 0; s < 2; s++) {
        int i = i0 + sg * 2 + s;
        float4 mxv = s ? mx1 : mx0;
        float4 a = m1[i * 32 + c4];
        float4 o;
        o.x = fmaxf(a.x + mxv.x, 0.f); o.y = fmaxf(a.y + mxv.y, 0.f);
        o.z = fmaxf(a.z + mxv.z, 0.f); o.w = fmaxf(a.w + mxv.w, 0.f);

        int grow = b * 256 + i;
        unsigned h0, l0, h1, l1;
        split2(o.x, o.y, h0, l0);
        split2(o.z, o.w, h1, l1);
        int kp = 64 + 2 * c4;            // message kpairs
        int a0 = a_addr(grow, kp, 16);
        int a1 = a_addr(grow, kp + 1, 16);
        g_xA[a0] = h0; g_xA[a0 + 128] = l0;
        g_xA[a1] = h1; g_xA[a1 + 128] = l1;
    }
}

// ---------------------------------------------------------------------------
// K3': out = relu(X @ Wu^T + bu), X = [z | m] in fragment layout, K = 256
// (16 ksteps). grid (64, 4), 256 threads = 8 warps (4m x 2n),
// warp tile 16m x 16n, block tile 64m x 32n. Software-pipelined like K1'.
// ---------------------------------------------------------------------------
__global__ __launch_bounds__(256) void k3_mma(
    const float* __restrict__ bu, float* __restrict__ out)
{
    const int lane = threadIdx.x & 31;
    const int wid  = threadIdx.x >> 5;
    const int wm   = wid >> 1, wn = wid & 1;
    const int g    = lane >> 2, t = lane & 3;
    const int row0 = blockIdx.x * 64 + wm * 16;
    const int n0   = blockIdx.y * 32 + wn * 16;
    const int mt   = row0 >> 4;
    const int ntb  = n0 >> 3;

    const unsigned* pa  = &g_xA[(mt * 16) * 256 + lane * 4];
    const unsigned* pb0 = &g_wuB[(ntb * 16) * 128 + lane * 2];
    const unsigned* pb1 = &g_wuB[((ntb + 1) * 16) * 128 + lane * 2];

    float c[2][4];
#pragma unroll
    for (int nt = 0; nt < 2; nt++)
#pragma unroll
        for (int q = 0; q < 4; q++) c[nt][q] = 0.f;

    uint4 ah  = *(const uint4*)pa;
    uint4 al  = *(const uint4*)(pa + 128);
    uint2 bh0 = *(const uint2*)pb0, bl0 = *(const uint2*)(pb0 + 64);
    uint2 bh1 = *(const uint2*)pb1, bl1 = *(const uint2*)(pb1 + 64);

#pragma unroll
    for (int ks = 0; ks < 16; ks++) {
        uint4 nah, nal; uint2 nbh0, nbl0, nbh1, nbl1;
        if (ks < 15) {
            const unsigned* qa = pa + (ks + 1) * 256;
            nah = *(const uint4*)qa;  nal = *(const uint4*)(qa + 128);
            const unsigned* q0 = pb0 + (ks + 1) * 128;
            nbh0 = *(const uint2*)q0; nbl0 = *(const uint2*)(q0 + 64);
            const unsigned* q1 = pb1 + (ks + 1) * 128;
            nbh1 = *(const uint2*)q1; nbl1 = *(const uint2*)(q1 + 64);
        }
        mma_bf16(c[0], ah.x, ah.y, ah.z, ah.w, bh0.x, bh0.y);
        mma_bf16(c[0], ah.x, ah.y, ah.z, ah.w, bl0.x, bl0.y);
        mma_bf16(c[0], al.x, al.y, al.z, al.w, bh0.x, bh0.y);
        mma_bf16(c[1], ah.x, ah.y, ah.z, ah.w, bh1.x, bh1.y);
        mma_bf16(c[1], ah.x, ah.y, ah.z, ah.w, bl1.x, bl1.y);
        mma_bf16(c[1], al.x, al.y, al.z, al.w, bh1.x, bh1.y);
        if (ks < 15) {
            ah = nah; al = nal;
            bh0 = nbh0; bl0 = nbl0; bh1 = nbh1; bl1 = nbl1;
        }
    }

#pragma unroll
    for (int nt = 0; nt < 2; nt++) {
        int n = n0 + nt * 8 + 2 * t;
        float bv0 = bu[n], bv1 = bu[n + 1];
        int r = row0 + g;
        out[r * 128 + n]           = fmaxf(c[nt][0] + bv0, 0.f);
        out[r * 128 + n + 1]       = fmaxf(c[nt][1] + bv1, 0.f);
        out[(r + 8) * 128 + n]     = fmaxf(c[nt][2] + bv0, 0.f);
        out[(r + 8) * 128 + n + 1] = fmaxf(c[nt][3] + bv1, 0.f);
    }
}

// ---------------------------------------------------------------------------
// Launch. Inputs (metadata order): z, P, W1, b1, W2, b2, Wu, bu.
// ---------------------------------------------------------------------------
extern "C" void kernel_launch(void* const* d_in, const int* in_sizes, int n_in,
                              void* d_out, int out_size)
{
    const float* z  = (const float*)d_in[0];
    const int*   P  = (const int*)  d_in[1];
    const float* W1 = (const float*)d_in[2];
    const float* b1 = (const float*)d_in[3];
    const float* W2 = (const float*)d_in[4];
    const float* b2 = (const float*)d_in[5];
    const float* Wu = (const float*)d_in[6];
    const float* bu = (const float*)d_in[7];
    float* out = (float*)d_out;

    p0_split<<<1152, 256>>>(z, W1, W2, Wu);

    dim3 g1(64, 8);
    k1_mma<<<g1, 256>>>(b1, b2);

    dim3 g2(16, 16);
    k2_maskmax<<<g2, 256>>>(P);

    dim3 g3(64, 4);
    k3_mma<<<g3, 256>>>(bu, out);
}